// round 1
// baseline (speedup 1.0000x reference)
#include <cuda_runtime.h>
#include <math.h>

#define N       12288
#define D_K     8
#define H1      32
#define H2      16
#define N_EDGES 6144
#define N_TRI   4096
#define CAP     64

// ---------------- device scratch (no allocations allowed) ----------------
__device__ float    g_q[N * D_K];
__device__ float    g_k[N * D_K];
__device__ float    g_v[N * D_K];
__device__ float    g_logits[N];
__device__ float    g_e[N];
__device__ int      g_cnt[N_TRI];
__device__ int      g_mem[N_TRI * CAP];
__device__ unsigned g_segmax[N_EDGES];
__device__ float    g_segsum[N_EDGES];

// monotone float <-> uint encoding for atomicMax on floats
__device__ __forceinline__ unsigned f2o(float f) {
    unsigned u = __float_as_uint(f);
    return (u & 0x80000000u) ? ~u : (u | 0x80000000u);
}
__device__ __forceinline__ float o2f(unsigned e) {
    return (e & 0x80000000u) ? __uint_as_float(e ^ 0x80000000u)
                             : __uint_as_float(~e);
}

__device__ __forceinline__ float gelu_exact(float x) {
    return 0.5f * x * (1.0f + erff(x * 0.70710678118654752f));
}

// ---------------- K0: zero per-replay state ----------------
__global__ void k_zero() {
    int i = blockIdx.x * blockDim.x + threadIdx.x;
    if (i < N_TRI)   g_cnt[i] = 0;
    if (i < N_EDGES) { g_segmax[i] = 0u; g_segsum[i] = 0.0f; }
}

// ---------------- K1: q,k,v projections + triangle bucketing ----------------
__global__ void k_qkv(const float* __restrict__ ef, const int* __restrict__ tri,
                      const float* __restrict__ Wq, const float* __restrict__ bq,
                      const float* __restrict__ Wk, const float* __restrict__ bk,
                      const float* __restrict__ Wv, const float* __restrict__ bv) {
    int i = blockIdx.x * blockDim.x + threadIdx.x;
    if (i >= N) return;
    float x0 = ef[2 * i + 0];
    float x1 = ef[2 * i + 1];
#pragma unroll
    for (int o = 0; o < D_K; o++) {
        g_q[i * D_K + o] = fmaf(x0, Wq[o * 2], fmaf(x1, Wq[o * 2 + 1], bq[o]));
        g_k[i * D_K + o] = fmaf(x0, Wk[o * 2], fmaf(x1, Wk[o * 2 + 1], bk[o]));
        g_v[i * D_K + o] = fmaf(x0, Wv[o * 2], fmaf(x1, Wv[o * 2 + 1], bv[o]));
    }
    int t = tri[i];
    int p = atomicAdd(&g_cnt[t], 1);
    if (p < CAP) g_mem[t * CAP + p] = i;
}

// ---------------- K2: grouped attention + MLP + logits + segment max ----------------
__global__ __launch_bounds__(128)
void k_main(const int* __restrict__ tri, const int* __restrict__ eids,
            const float* __restrict__ W1, const float* __restrict__ b1,
            const float* __restrict__ ln1g, const float* __restrict__ ln1b,
            const float* __restrict__ rmsw,
            const float* __restrict__ Wr, const float* __restrict__ br,
            const float* __restrict__ ln2g, const float* __restrict__ ln2b,
            const float* __restrict__ W2, const float* __restrict__ b2,
            const float* __restrict__ W3, const float* __restrict__ b3) {
    __shared__ float sW1[H1 * D_K], sWr[H1 * H1], sW2[H2 * H1];
    __shared__ float sb1[H1], sg1[H1], sB1[H1], srw[H1], sbr[H1], sg2[H1], sB2[H1];
    __shared__ float sb2[H2], sW3[H2];
    __shared__ float sb3;

    int tid = threadIdx.x;
    for (int j = tid; j < H1 * D_K; j += blockDim.x) sW1[j] = W1[j];
    for (int j = tid; j < H1 * H1;  j += blockDim.x) sWr[j] = Wr[j];
    for (int j = tid; j < H2 * H1;  j += blockDim.x) sW2[j] = W2[j];
    if (tid < H1) {
        sb1[tid] = b1[tid];  sg1[tid] = ln1g[tid]; sB1[tid] = ln1b[tid];
        srw[tid] = rmsw[tid]; sbr[tid] = br[tid];
        sg2[tid] = ln2g[tid]; sB2[tid] = ln2b[tid];
    }
    if (tid < H2) { sb2[tid] = b2[tid]; sW3[tid] = W3[tid]; }
    if (tid == 0) sb3 = b3[0];
    __syncthreads();

    int i = blockIdx.x * blockDim.x + tid;
    if (i >= N) return;

    // ---- grouped attention ----
    float q[D_K];
#pragma unroll
    for (int o = 0; o < D_K; o++) q[o] = g_q[i * D_K + o];

    int t = tri[i];
    int c = min(g_cnt[t], CAP);
    const float isq = 0.35355339059327373f;  // 1/sqrt(8)

    float m = -1e30f;
    for (int jj = 0; jj < c; jj++) {
        int j = g_mem[t * CAP + jj];
        float s = 0.0f;
#pragma unroll
        for (int o = 0; o < D_K; o++) s = fmaf(q[o], g_k[j * D_K + o], s);
        m = fmaxf(m, s * isq);
    }
    float se = 0.0f, acc[D_K];
#pragma unroll
    for (int o = 0; o < D_K; o++) acc[o] = 0.0f;
    for (int jj = 0; jj < c; jj++) {
        int j = g_mem[t * CAP + jj];
        float s = 0.0f;
#pragma unroll
        for (int o = 0; o < D_K; o++) s = fmaf(q[o], g_k[j * D_K + o], s);
        float e = expf(s * isq - m);
        se += e;
#pragma unroll
        for (int o = 0; o < D_K; o++) acc[o] = fmaf(e, g_v[j * D_K + o], acc[o]);
    }
    float inv_se = 1.0f / se;
    float att[D_K];
#pragma unroll
    for (int o = 0; o < D_K; o++) att[o] = acc[o] * inv_se;

    // ---- MLP ----
    float h[H1];
#pragma unroll
    for (int o = 0; o < H1; o++) {
        float s = sb1[o];
#pragma unroll
        for (int kk = 0; kk < D_K; kk++) s = fmaf(att[kk], sW1[o * D_K + kk], s);
        h[o] = s;
    }
    // layernorm 1 + gelu
    {
        float mu = 0.0f;
#pragma unroll
        for (int o = 0; o < H1; o++) mu += h[o];
        mu *= (1.0f / H1);
        float var = 0.0f;
#pragma unroll
        for (int o = 0; o < H1; o++) { float d = h[o] - mu; var = fmaf(d, d, var); }
        var *= (1.0f / H1);
        float inv = rsqrtf(var + 1e-5f);
#pragma unroll
        for (int o = 0; o < H1; o++)
            h[o] = gelu_exact((h[o] - mu) * inv * sg1[o] + sB1[o]);
    }
    // rmsnorm -> linear -> relu -> residual
    {
        float ss = 0.0f;
#pragma unroll
        for (int o = 0; o < H1; o++) ss = fmaf(h[o], h[o], ss);
        float rms = sqrtf(ss * (1.0f / H1));
        float inv = 1.0f / (rms + 1e-6f);
        float xn[H1];
#pragma unroll
        for (int o = 0; o < H1; o++) xn[o] = h[o] * inv * srw[o];
#pragma unroll
        for (int o = 0; o < H1; o++) {
            float s = sbr[o];
#pragma unroll
            for (int kk = 0; kk < H1; kk++) s = fmaf(xn[kk], sWr[o * H1 + kk], s);
            h[o] += fmaxf(s, 0.0f);
        }
    }
    // layernorm 2
    {
        float mu = 0.0f;
#pragma unroll
        for (int o = 0; o < H1; o++) mu += h[o];
        mu *= (1.0f / H1);
        float var = 0.0f;
#pragma unroll
        for (int o = 0; o < H1; o++) { float d = h[o] - mu; var = fmaf(d, d, var); }
        var *= (1.0f / H1);
        float inv = rsqrtf(var + 1e-5f);
#pragma unroll
        for (int o = 0; o < H1; o++)
            h[o] = (h[o] - mu) * inv * sg2[o] + sB2[o];
    }
    // linear 32->16 + gelu, linear 16->1
    float lg = sb3;
#pragma unroll
    for (int o = 0; o < H2; o++) {
        float s = sb2[o];
#pragma unroll
        for (int kk = 0; kk < H1; kk++) s = fmaf(h[kk], sW2[o * H1 + kk], s);
        lg = fmaf(gelu_exact(s), sW3[o], lg);
    }
    g_logits[i] = lg;
    atomicMax(&g_segmax[eids[i]], f2o(lg));
}

// ---------------- K3: exp + segment sum ----------------
__global__ void k_exp(const int* __restrict__ eids) {
    int i = blockIdx.x * blockDim.x + threadIdx.x;
    if (i >= N) return;
    int s = eids[i];
    float mx = o2f(g_segmax[s]);
    float e = expf(g_logits[i] - mx);
    g_e[i] = e;
    atomicAdd(&g_segsum[s], e);
}

// ---------------- K4: normalize ----------------
__global__ void k_out(const int* __restrict__ eids, float* __restrict__ out) {
    int i = blockIdx.x * blockDim.x + threadIdx.x;
    if (i >= N) return;
    out[i] = g_e[i] / g_segsum[eids[i]];
}

extern "C" void kernel_launch(void* const* d_in, const int* in_sizes, int n_in,
                              void* d_out, int out_size) {
    const float* ef   = (const float*)d_in[0];
    const int*   eids = (const int*)  d_in[1];
    const int*   tri  = (const int*)  d_in[2];
    const float* Wq = (const float*)d_in[3];  const float* bq = (const float*)d_in[4];
    const float* Wk = (const float*)d_in[5];  const float* bk = (const float*)d_in[6];
    const float* Wv = (const float*)d_in[7];  const float* bv = (const float*)d_in[8];
    const float* W1 = (const float*)d_in[9];  const float* b1 = (const float*)d_in[10];
    const float* g1 = (const float*)d_in[11]; const float* B1 = (const float*)d_in[12];
    const float* rw = (const float*)d_in[13];
    const float* Wr = (const float*)d_in[14]; const float* br = (const float*)d_in[15];
    const float* g2 = (const float*)d_in[16]; const float* B2 = (const float*)d_in[17];
    const float* W2 = (const float*)d_in[18]; const float* b2 = (const float*)d_in[19];
    const float* W3 = (const float*)d_in[20]; const float* b3 = (const float*)d_in[21];
    float* out = (float*)d_out;

    k_zero<<<(N_EDGES + 255) / 256, 256>>>();
    k_qkv <<<(N + 255) / 256, 256>>>(ef, tri, Wq, bq, Wk, bk, Wv, bv);
    k_main<<<(N + 127) / 128, 128>>>(tri, eids, W1, b1, g1, B1, rw, Wr, br,
                                     g2, B2, W2, b2, W3, b3);
    k_exp <<<(N + 255) / 256, 256>>>(eids);
    k_out <<<(N + 255) / 256, 256>>>(eids, out);
}